// round 1
// baseline (speedup 1.0000x reference)
#include <cuda_runtime.h>
#include <math.h>

// Problem constants
#define HEADS   16
#define DH      64
#define NQ      2048
#define NM      2048
#define BATCH   4
#define DMODEL  1024
#define ROWS_Q  (BATCH * NQ)   // 8192

// Scratch (static device globals: allocation-free)
__device__ float g_q[BATCH * HEADS * NQ * DH];   // 32 MB, layout [b,h,n,d]
__device__ float g_k[BATCH * HEADS * NM * DH];   // 32 MB, layout [b,h,m,d]
__device__ float g_v[BATCH * HEADS * NM * DH];   // 32 MB, layout [b,h,m,d]
__device__ float g_ao[ROWS_Q * DMODEL];          // 32 MB, layout [b,n,(h d)]

// ----------------------------------------------------------------------------
// GEMM:  C[i,j] = alpha * sum_k A[i,k] * W[j,k]   (A: [8192,1024], W: [1024,1024])
// mode 0: scatter C to head layout [b,h,n,d] (i = b*2048+n, j = h*64+d)
// mode 1: row-major C[i*1024+j] + bias[j]
// Tiling: 128x128x16, 256 threads, 8x8 microtile.
// ----------------------------------------------------------------------------
__global__ __launch_bounds__(256, 2)
void gemm_nt_kernel(const float* __restrict__ A, const float* __restrict__ W,
                    float* __restrict__ C, const float* __restrict__ bias,
                    float alpha, int mode)
{
    __shared__ float As[16 * 132];
    __shared__ float Bs[16 * 132];

    const int K = DMODEL;
    const int tid = threadIdx.x;
    const int tx = tid & 15;
    const int ty = tid >> 4;
    const int row0 = blockIdx.y * 128;
    const int col0 = blockIdx.x * 128;

    float acc[8][8];
#pragma unroll
    for (int m = 0; m < 8; ++m)
#pragma unroll
        for (int n = 0; n < 8; ++n) acc[m][n] = 0.f;

    for (int k0 = 0; k0 < K; k0 += 16) {
#pragma unroll
        for (int i = 0; i < 2; ++i) {
            int idx = tid + i * 256;        // 0..511
            int r   = idx >> 2;             // 0..127
            int c4  = idx & 3;              // 0..3
            float4 va = *(const float4*)(A + (size_t)(row0 + r) * K + k0 + c4 * 4);
            As[(c4 * 4 + 0) * 132 + r] = va.x;
            As[(c4 * 4 + 1) * 132 + r] = va.y;
            As[(c4 * 4 + 2) * 132 + r] = va.z;
            As[(c4 * 4 + 3) * 132 + r] = va.w;
            float4 vb = *(const float4*)(W + (size_t)(col0 + r) * K + k0 + c4 * 4);
            Bs[(c4 * 4 + 0) * 132 + r] = vb.x;
            Bs[(c4 * 4 + 1) * 132 + r] = vb.y;
            Bs[(c4 * 4 + 2) * 132 + r] = vb.z;
            Bs[(c4 * 4 + 3) * 132 + r] = vb.w;
        }
        __syncthreads();

#pragma unroll
        for (int k = 0; k < 16; ++k) {
            float ra[8], rb[8];
            *(float4*)&ra[0] = *(float4*)&As[k * 132 + ty * 8];
            *(float4*)&ra[4] = *(float4*)&As[k * 132 + ty * 8 + 4];
            *(float4*)&rb[0] = *(float4*)&Bs[k * 132 + tx * 8];
            *(float4*)&rb[4] = *(float4*)&Bs[k * 132 + tx * 8 + 4];
#pragma unroll
            for (int m = 0; m < 8; ++m)
#pragma unroll
                for (int n = 0; n < 8; ++n)
                    acc[m][n] += ra[m] * rb[n];
        }
        __syncthreads();
    }

    if (mode == 0) {
        // scatter to [b,h,n,d]; each thread's 8 cols stay within one head
        const int gj0 = col0 + tx * 8;
        const int hh  = gj0 >> 6;
        const int d0  = gj0 & 63;
#pragma unroll
        for (int m = 0; m < 8; ++m) {
            int gi = row0 + ty * 8 + m;
            int b  = gi >> 11;
            int n  = gi & 2047;
            float* dst = C + (((size_t)b * HEADS + hh) * NQ + n) * DH + d0;
            float4 v0 = make_float4(acc[m][0] * alpha, acc[m][1] * alpha,
                                    acc[m][2] * alpha, acc[m][3] * alpha);
            float4 v1 = make_float4(acc[m][4] * alpha, acc[m][5] * alpha,
                                    acc[m][6] * alpha, acc[m][7] * alpha);
            *(float4*)dst       = v0;
            *(float4*)(dst + 4) = v1;
        }
    } else {
        const int gj0 = col0 + tx * 8;
        float4 bv0 = *(const float4*)(bias + gj0);
        float4 bv1 = *(const float4*)(bias + gj0 + 4);
#pragma unroll
        for (int m = 0; m < 8; ++m) {
            int gi = row0 + ty * 8 + m;
            float* dst = C + (size_t)gi * DMODEL + gj0;
            float4 v0 = make_float4(acc[m][0] + bv0.x, acc[m][1] + bv0.y,
                                    acc[m][2] + bv0.z, acc[m][3] + bv0.w);
            float4 v1 = make_float4(acc[m][4] + bv1.x, acc[m][5] + bv1.y,
                                    acc[m][6] + bv1.z, acc[m][7] + bv1.w);
            *(float4*)dst       = v0;
            *(float4*)(dst + 4) = v1;
        }
    }
}

// ----------------------------------------------------------------------------
// Flash attention: one block handles (bh, 64 query rows), loops over M in
// 64-row K/V tiles with online softmax. fp32 everywhere. Scale folded into Q.
// Output written merged-head to g_ao[b, n, h*64+d].
// ----------------------------------------------------------------------------
#define BR  64
#define BC  64
#define LDT 68   // smem row stride (pad: conflict-free, float4-aligned)

__global__ __launch_bounds__(256, 2)
void flash_kernel(const float* __restrict__ q, const float* __restrict__ kmat,
                  const float* __restrict__ vmat, float* __restrict__ ao)
{
    extern __shared__ float sm[];
    float* Qs    = sm;                 // 64*68
    float* Ks    = Qs + BR * LDT;      // 64*68
    float* Vs    = Ks + BC * LDT;      // 64*68
    float* Ps    = Vs + BC * LDT;      // 64*68
    float* red   = Ps + BR * LDT;      // 16*64
    float* m_row = red + 16 * 64;      // 64
    float* l_row = m_row + BR;         // 64

    const int tid = threadIdx.x;
    const int tx  = tid & 15;
    const int ty  = tid >> 4;
    const int bh  = blockIdx.y;
    const int q0  = blockIdx.x * BR;

    const float* qb = q    + ((size_t)bh * NQ + q0) * DH;
    const float* kb = kmat + (size_t)bh * NM * DH;
    const float* vb = vmat + (size_t)bh * NM * DH;

    // load Q tile
    for (int i = tid; i < BR * 16; i += 256) {
        int r = i >> 4, c4 = i & 15;
        *(float4*)&Qs[r * LDT + c4 * 4] = *(const float4*)(qb + r * DH + c4 * 4);
    }
    if (tid < BR) { m_row[tid] = -1e30f; l_row[tid] = 0.f; }

    float o[4][4] = {};
    const int r0 = ty * 4;
    const int c0 = tx * 4;

    for (int m0 = 0; m0 < NM; m0 += BC) {
        __syncthreads();   // S0: previous O-update done (and Q/stat init visible)

        // load K,V tiles
        for (int i = tid; i < BC * 16; i += 256) {
            int r = i >> 4, c4 = i & 15;
            *(float4*)&Ks[r * LDT + c4 * 4] = *(const float4*)(kb + (size_t)(m0 + r) * DH + c4 * 4);
            *(float4*)&Vs[r * LDT + c4 * 4] = *(const float4*)(vb + (size_t)(m0 + r) * DH + c4 * 4);
        }
        __syncthreads();   // S1

        // S = Q * K^T  (scale already in Q)
        float s[4][4] = {};
#pragma unroll
        for (int k = 0; k < DH; k += 4) {
            float a[4][4], bm[4][4];
#pragma unroll
            for (int m = 0; m < 4; ++m)
                *(float4*)a[m] = *(float4*)&Qs[(r0 + m) * LDT + k];
#pragma unroll
            for (int n = 0; n < 4; ++n)
                *(float4*)bm[n] = *(float4*)&Ks[(c0 + n) * LDT + k];
#pragma unroll
            for (int m = 0; m < 4; ++m)
#pragma unroll
                for (int n = 0; n < 4; ++n)
                    s[m][n] += a[m][0] * bm[n][0] + a[m][1] * bm[n][1]
                             + a[m][2] * bm[n][2] + a[m][3] * bm[n][3];
        }

        // tile row-max partials
        float mold[4];
#pragma unroll
        for (int m = 0; m < 4; ++m) {
            mold[m] = m_row[r0 + m];
            float t = s[m][0];
            t = fmaxf(t, s[m][1]); t = fmaxf(t, s[m][2]); t = fmaxf(t, s[m][3]);
            red[tx * 64 + r0 + m] = t;
        }
        __syncthreads();   // S2

        float nm[4], fac[4], rs[4];
#pragma unroll
        for (int m = 0; m < 4; ++m) {
            float t = -1e30f;
#pragma unroll
            for (int j = 0; j < 16; ++j) t = fmaxf(t, red[j * 64 + r0 + m]);
            float nmv = fmaxf(mold[m], t);
            nm[m]  = nmv;
            fac[m] = __expf(mold[m] - nmv);
            float rsum = 0.f;
#pragma unroll
            for (int n = 0; n < 4; ++n) {
                float p = __expf(s[m][n] - nmv);
                s[m][n] = p;
                rsum += p;
            }
            rs[m] = rsum;
        }
        __syncthreads();   // S3: all red(max) reads done

#pragma unroll
        for (int m = 0; m < 4; ++m) red[tx * 64 + r0 + m] = rs[m];
        if (tx == 0) {
#pragma unroll
            for (int m = 0; m < 4; ++m) m_row[r0 + m] = nm[m];
        }
        __syncthreads();   // S4

#pragma unroll
        for (int m = 0; m < 4; ++m) {
            float t = 0.f;
#pragma unroll
            for (int j = 0; j < 16; ++j) t += red[j * 64 + r0 + m];
            if (tx == 0) l_row[r0 + m] = l_row[r0 + m] * fac[m] + t;
#pragma unroll
            for (int n = 0; n < 4; ++n) o[m][n] *= fac[m];
            *(float4*)&Ps[(r0 + m) * LDT + c0] =
                make_float4(s[m][0], s[m][1], s[m][2], s[m][3]);
        }
        __syncthreads();   // S5: Ps + l_row visible

        // O += P * V
#pragma unroll
        for (int k = 0; k < BC; k += 4) {
            float p4[4][4], v4[4][4];
#pragma unroll
            for (int m = 0; m < 4; ++m)
                *(float4*)p4[m] = *(float4*)&Ps[(r0 + m) * LDT + k];
#pragma unroll
            for (int j = 0; j < 4; ++j)
                *(float4*)v4[j] = *(float4*)&Vs[(k + j) * LDT + c0];
#pragma unroll
            for (int m = 0; m < 4; ++m)
#pragma unroll
                for (int n = 0; n < 4; ++n)
                    o[m][n] += p4[m][0] * v4[0][n] + p4[m][1] * v4[1][n]
                             + p4[m][2] * v4[2][n] + p4[m][3] * v4[3][n];
        }
    }

    // epilogue: divide by l, write merged-head output
    const int b  = bh >> 4;
    const int hh = bh & 15;
#pragma unroll
    for (int m = 0; m < 4; ++m) {
        float inv = 1.0f / l_row[r0 + m];
        float4 v = make_float4(o[m][0] * inv, o[m][1] * inv,
                               o[m][2] * inv, o[m][3] * inv);
        *(float4*)&ao[(size_t)(b * NQ + q0 + r0 + m) * DMODEL + hh * DH + c0] = v;
    }
}

// ----------------------------------------------------------------------------
extern "C" void kernel_launch(void* const* d_in, const int* in_sizes, int n_in,
                              void* d_out, int out_size)
{
    const float* x   = (const float*)d_in[0];
    const float* ctx = (const float*)d_in[1];
    const float* Wq  = (const float*)d_in[2];
    const float* Wk  = (const float*)d_in[3];
    const float* Wv  = (const float*)d_in[4];
    const float* Wo  = (const float*)d_in[5];
    const float* bo  = (const float*)d_in[6];
    float* out = (float*)d_out;

    float *q, *k, *v, *ao;
    cudaGetSymbolAddress((void**)&q,  g_q);
    cudaGetSymbolAddress((void**)&k,  g_k);
    cudaGetSymbolAddress((void**)&v,  g_v);
    cudaGetSymbolAddress((void**)&ao, g_ao);

    const int smem_flash = (4 * BR * LDT + 16 * 64 + 2 * BR) * (int)sizeof(float); // 74240
    cudaFuncSetAttribute(flash_kernel, cudaFuncAttributeMaxDynamicSharedMemorySize, smem_flash);

    dim3 ggrid(DMODEL / 128, ROWS_Q / 128);   // (8, 64)
    const float scale = 0.125f;               // 64^-0.5, folded into Q

    gemm_nt_kernel<<<ggrid, 256>>>(x,   Wq, q, nullptr, scale, 0);
    gemm_nt_kernel<<<ggrid, 256>>>(ctx, Wk, k, nullptr, 1.0f,  0);
    gemm_nt_kernel<<<ggrid, 256>>>(ctx, Wv, v, nullptr, 1.0f,  0);

    flash_kernel<<<dim3(NQ / BR, BATCH * HEADS), 256, smem_flash>>>(q, k, v, ao);

    gemm_nt_kernel<<<ggrid, 256>>>(ao, Wo, out, bo, 1.0f, 1);
}

// round 3
// speedup vs baseline: 3.9991x; 3.9991x over previous
#include <cuda_runtime.h>
#include <cuda_bf16.h>
#include <cuda_fp16.h>
#include <math.h>
#include <stdint.h>

// Problem constants
#define HEADS   16
#define DH      64
#define NQ      2048
#define NM      2048
#define BATCH   4
#define DMODEL  1024
#define ROWS_Q  (BATCH * NQ)   // 8192

// ---------------------------------------------------------------------------
// Scratch (static device globals: allocation-free)
// ---------------------------------------------------------------------------
__device__ __nv_bfloat16 g_xh[ROWS_Q * DMODEL];
__device__ __nv_bfloat16 g_xl[ROWS_Q * DMODEL];
__device__ __nv_bfloat16 g_ch[ROWS_Q * DMODEL];
__device__ __nv_bfloat16 g_cl[ROWS_Q * DMODEL];
__device__ __nv_bfloat16 g_wh[4 * DMODEL * DMODEL];
__device__ __nv_bfloat16 g_wl[4 * DMODEL * DMODEL];
__device__ __half        g_q16[ROWS_Q * DMODEL];
__device__ __half        g_k16[ROWS_Q * DMODEL];
__device__ __half        g_v16[ROWS_Q * DMODEL];
__device__ __nv_bfloat16 g_aoh[ROWS_Q * DMODEL];
__device__ __nv_bfloat16 g_aol[ROWS_Q * DMODEL];

// ---------------------------------------------------------------------------
// Portable (compute_103-safe) helpers: mma.sync / ldmatrix / cp.async
// ---------------------------------------------------------------------------
__device__ __forceinline__ uint32_t smem_u32(const void* p) {
    uint32_t a;
    asm("{ .reg .u64 t; cvta.to.shared.u64 t, %1; cvt.u32.u64 %0, t; }"
        : "=r"(a) : "l"(p));
    return a;
}

__device__ __forceinline__ void mma_bf16(float* c, const uint32_t* a, const uint32_t* b) {
    asm volatile("mma.sync.aligned.m16n8k16.row.col.f32.bf16.bf16.f32 "
        "{%0,%1,%2,%3}, {%4,%5,%6,%7}, {%8,%9}, {%0,%1,%2,%3};"
        : "+f"(c[0]), "+f"(c[1]), "+f"(c[2]), "+f"(c[3])
        : "r"(a[0]), "r"(a[1]), "r"(a[2]), "r"(a[3]), "r"(b[0]), "r"(b[1]));
}

__device__ __forceinline__ void mma_f16(float* c, const uint32_t* a, const uint32_t* b) {
    asm volatile("mma.sync.aligned.m16n8k16.row.col.f32.f16.f16.f32 "
        "{%0,%1,%2,%3}, {%4,%5,%6,%7}, {%8,%9}, {%0,%1,%2,%3};"
        : "+f"(c[0]), "+f"(c[1]), "+f"(c[2]), "+f"(c[3])
        : "r"(a[0]), "r"(a[1]), "r"(a[2]), "r"(a[3]), "r"(b[0]), "r"(b[1]));
}

__device__ __forceinline__ void ldm_x4(uint32_t* r, uint32_t a) {
    asm volatile("ldmatrix.sync.aligned.m8n8.x4.shared.b16 {%0,%1,%2,%3}, [%4];"
        : "=r"(r[0]), "=r"(r[1]), "=r"(r[2]), "=r"(r[3]) : "r"(a));
}
__device__ __forceinline__ void ldm_x2(uint32_t* r, uint32_t a) {
    asm volatile("ldmatrix.sync.aligned.m8n8.x2.shared.b16 {%0,%1}, [%2];"
        : "=r"(r[0]), "=r"(r[1]) : "r"(a));
}
__device__ __forceinline__ void ldm_x2t(uint32_t* r, uint32_t a) {
    asm volatile("ldmatrix.sync.aligned.m8n8.x2.trans.shared.b16 {%0,%1}, [%2];"
        : "=r"(r[0]), "=r"(r[1]) : "r"(a));
}

__device__ __forceinline__ void cp16(uint32_t dst, const void* src) {
    asm volatile("cp.async.cg.shared.global [%0], [%1], 16;" :: "r"(dst), "l"(src));
}

__device__ __forceinline__ uint32_t pack_h2(float a, float b) {
    __half2 h = __floats2half2_rn(a, b);
    return *(uint32_t*)&h;
}

// ---------------------------------------------------------------------------
// Split fp32 -> (bf16 hi, bf16 lo)
// ---------------------------------------------------------------------------
__global__ void split_kernel(const float* __restrict__ in,
                             __nv_bfloat16* __restrict__ hi,
                             __nv_bfloat16* __restrict__ lo, int n4)
{
    int i = blockIdx.x * blockDim.x + threadIdx.x;
    if (i >= n4) return;
    float4 v = ((const float4*)in)[i];
    __nv_bfloat16 h0 = __float2bfloat16(v.x);
    __nv_bfloat16 h1 = __float2bfloat16(v.y);
    __nv_bfloat16 h2 = __float2bfloat16(v.z);
    __nv_bfloat16 h3 = __float2bfloat16(v.w);
    __nv_bfloat16 l0 = __float2bfloat16(v.x - __bfloat162float(h0));
    __nv_bfloat16 l1 = __float2bfloat16(v.y - __bfloat162float(h1));
    __nv_bfloat16 l2 = __float2bfloat16(v.z - __bfloat162float(h2));
    __nv_bfloat16 l3 = __float2bfloat16(v.w - __bfloat162float(h3));
    __nv_bfloat162* hp = (__nv_bfloat162*)hi;
    __nv_bfloat162* lp = (__nv_bfloat162*)lo;
    hp[2 * i]     = __nv_bfloat162{h0, h1};
    hp[2 * i + 1] = __nv_bfloat162{h2, h3};
    lp[2 * i]     = __nv_bfloat162{l0, l1};
    lp[2 * i + 1] = __nv_bfloat162{l2, l3};
}

// ---------------------------------------------------------------------------
// HMMA bf16x3 GEMM:  C[i,j] = alpha * sum_k A[i,k] * W[j,k]  (+ bias[j])
// A [8192,1024], W [NCOL-major 1024,1024], both K-major.
// Tile 128x128x32, 8 warps (2x4), warp tile 64x32, cp.async double buffer.
// fp16_out=1: C is __half.  fp16_out=0: C is float with bias.
// ---------------------------------------------------------------------------
#define BK          32
#define GPAD        40                      // bf16 elems per smem row (80B)
#define MAT_ELEMS   (128 * GPAD)
#define MAT_BYTES   (MAT_ELEMS * 2)         // 10240
#define STAGE_BYTES (4 * MAT_BYTES)         // 40960
#define GEMM_DSMEM  (2 * STAGE_BYTES)       // 81920

__device__ __forceinline__ void g_load_stage(
    uint32_t sbase,
    const __nv_bfloat16* __restrict__ Ah, const __nv_bfloat16* __restrict__ Al,
    const __nv_bfloat16* __restrict__ Bh, const __nv_bfloat16* __restrict__ Bl,
    int row0, int col0, int k0, int lrow, int lc16)
{
#pragma unroll
    for (int hf = 0; hf < 2; ++hf) {
        int r = lrow + hf * 64;
        uint32_t so = sbase + (uint32_t)(r * GPAD + lc16 * 8) * 2;
        size_t goA = (size_t)(row0 + r) * DMODEL + k0 + lc16 * 8;
        size_t goB = (size_t)(col0 + r) * DMODEL + k0 + lc16 * 8;
        cp16(so,                 Ah + goA);
        cp16(so + MAT_BYTES,     Al + goA);
        cp16(so + 2 * MAT_BYTES, Bh + goB);
        cp16(so + 3 * MAT_BYTES, Bl + goB);
    }
}

__global__ __launch_bounds__(256, 1)
void gemm_mma(const __nv_bfloat16* __restrict__ Ah, const __nv_bfloat16* __restrict__ Al,
              const __nv_bfloat16* __restrict__ Bh, const __nv_bfloat16* __restrict__ Bl,
              void* __restrict__ Cout, const float* __restrict__ bias,
              float alpha, int fp16_out)
{
    extern __shared__ __align__(16) char gsm[];
    const int tid  = threadIdx.x;
    const int lane = tid & 31;
    const int wid  = tid >> 5;
    const int wm   = wid >> 2;      // 0..1 -> 64 rows
    const int wn   = wid & 3;       // 0..3 -> 32 cols
    const int row0 = blockIdx.y * 128;
    const int col0 = blockIdx.x * 128;
    const int lrow = tid >> 2;      // 0..63
    const int lc16 = tid & 3;       // 16B chunk in 64B row

    uint32_t smb = smem_u32(gsm);

    float acc[4][4][4] = {};

    g_load_stage(smb, Ah, Al, Bh, Bl, row0, col0, 0, lrow, lc16);
    asm volatile("cp.async.commit_group;" ::: "memory");

    for (int c = 0; c < DMODEL / BK; ++c) {
        const int buf = c & 1;
        if (c + 1 < DMODEL / BK) {
            g_load_stage(smb + (buf ^ 1) * STAGE_BYTES, Ah, Al, Bh, Bl,
                         row0, col0, (c + 1) * BK, lrow, lc16);
            asm volatile("cp.async.commit_group;" ::: "memory");
            asm volatile("cp.async.wait_group 1;" ::: "memory");
        } else {
            asm volatile("cp.async.wait_group 0;" ::: "memory");
        }
        __syncthreads();

        uint32_t sAh = smb + buf * STAGE_BYTES;
        uint32_t sAl = sAh + MAT_BYTES;
        uint32_t sBh = sAh + 2 * MAT_BYTES;
        uint32_t sBl = sAh + 3 * MAT_BYTES;

#pragma unroll
        for (int ks = 0; ks < 2; ++ks) {
            uint32_t ah[4][4], al[4][4], bh[4][2], bl[4][2];
            const int ar = wm * 64 + (lane & 15);
            const int ac = ks * 16 + (lane >> 4) * 8;
#pragma unroll
            for (int mt = 0; mt < 4; ++mt) {
                uint32_t off = (uint32_t)((ar + mt * 16) * GPAD + ac) * 2;
                ldm_x4(ah[mt], sAh + off);
                ldm_x4(al[mt], sAl + off);
            }
            const int br = wn * 32 + (lane & 7);
            const int bc = ks * 16 + ((lane >> 3) & 1) * 8;
#pragma unroll
            for (int nt = 0; nt < 4; ++nt) {
                uint32_t off = (uint32_t)((br + nt * 8) * GPAD + bc) * 2;
                ldm_x2(bh[nt], sBh + off);
                ldm_x2(bl[nt], sBl + off);
            }
#pragma unroll
            for (int mt = 0; mt < 4; ++mt)
#pragma unroll
                for (int nt = 0; nt < 4; ++nt) {
                    mma_bf16(acc[mt][nt], ah[mt], bh[nt]);
                    mma_bf16(acc[mt][nt], ah[mt], bl[nt]);
                    mma_bf16(acc[mt][nt], al[mt], bh[nt]);
                }
        }
        __syncthreads();
    }

    // Epilogue
    if (fp16_out) {
        __half* Ch = (__half*)Cout;
#pragma unroll
        for (int mt = 0; mt < 4; ++mt)
#pragma unroll
            for (int nt = 0; nt < 4; ++nt) {
                int rr = row0 + wm * 64 + mt * 16 + (lane >> 2);
                int cc = col0 + wn * 32 + nt * 8 + (lane & 3) * 2;
#pragma unroll
                for (int h = 0; h < 2; ++h) {
                    int r = rr + h * 8;
                    __half2 hv = __floats2half2_rn(acc[mt][nt][h * 2] * alpha,
                                                   acc[mt][nt][h * 2 + 1] * alpha);
                    *(__half2*)(Ch + (size_t)r * DMODEL + cc) = hv;
                }
            }
    } else {
        float* Cf = (float*)Cout;
#pragma unroll
        for (int mt = 0; mt < 4; ++mt)
#pragma unroll
            for (int nt = 0; nt < 4; ++nt) {
                int rr = row0 + wm * 64 + mt * 16 + (lane >> 2);
                int cc = col0 + wn * 32 + nt * 8 + (lane & 3) * 2;
                float b0 = bias[cc], b1 = bias[cc + 1];
#pragma unroll
                for (int h = 0; h < 2; ++h) {
                    int r = rr + h * 8;
                    float2 v = make_float2(acc[mt][nt][h * 2] + b0,
                                           acc[mt][nt][h * 2 + 1] + b1);
                    *(float2*)(Cf + (size_t)r * DMODEL + cc) = v;
                }
            }
    }
}

// ---------------------------------------------------------------------------
// Flash attention, fp16 HMMA (FA2 style).
// CTA: 128 q-rows x one (b,h).  8 warps: wm 0..3 (32 rows), wn 0..1 (32 kv).
// kv chunks of 64.  Writes bf16 hi/lo of merged-head output directly.
// ---------------------------------------------------------------------------
#define FPAD 72   // fp16 elems per smem row (144B)

__global__ __launch_bounds__(256)
void flash_mma(const __half* __restrict__ q, const __half* __restrict__ kk,
               const __half* __restrict__ vv,
               __nv_bfloat16* __restrict__ aoh, __nv_bfloat16* __restrict__ aol)
{
    __shared__ __align__(16) char fsm[128 * FPAD * 2 + 64 * FPAD * 2 * 2 + 512 * 4];
    __half* Qs  = (__half*)fsm;                          // 128 x FPAD   (18432 B)
    __half* Ks  = (__half*)(fsm + 18432);                // 64 x FPAD    ( 9216 B)
    __half* Vs  = (__half*)(fsm + 27648);                // 64 x FPAD    ( 9216 B)
    float*  red = (float*)(fsm + 36864);                 // [2][2][128]  ( 2048 B)

    const int tid  = threadIdx.x;
    const int lane = tid & 31;
    const int wid  = tid >> 5;
    const int wm   = wid >> 1;      // 0..3
    const int wn   = wid & 1;       // 0..1
    const int bh   = blockIdx.y;
    const int b    = bh >> 4;
    const int hh   = bh & 15;
    const int q0   = blockIdx.x * 128;
    const int g    = lane >> 2;
    const int qd   = lane & 3;

    const __half* qg = q  + (size_t)(b * NQ + q0) * DMODEL + hh * DH;
    const __half* kg = kk + (size_t)b * NM * DMODEL + hh * DH;
    const __half* vg = vv + (size_t)b * NM * DMODEL + hh * DH;

    // load Q tile (128 x 64 fp16)
    {
        int r = tid >> 3, c8 = tid & 7;
#pragma unroll
        for (int i = 0; i < 4; ++i) {
            int rr = r + i * 32;
            *(uint4*)(Qs + rr * FPAD + c8 * 8) =
                *(const uint4*)(qg + (size_t)rr * DMODEL + c8 * 8);
        }
    }

    float m_[2][2], l_[2][2];
#pragma unroll
    for (int a = 0; a < 2; ++a)
#pragma unroll
        for (int h = 0; h < 2; ++h) { m_[a][h] = -1e30f; l_[a][h] = 0.f; }
    float O[2][8][4] = {};

    const uint32_t qbase = smem_u32(Qs);
    const uint32_t kbase = smem_u32(Ks);
    const uint32_t vbase = smem_u32(Vs);

    for (int m0 = 0; m0 < NM; m0 += 64) {
        __syncthreads();   // K/V smem safe to overwrite
        {
            int r = tid >> 3, c8 = tid & 7;
#pragma unroll
            for (int i = 0; i < 2; ++i) {
                int rr = r + i * 32;
                *(uint4*)(Ks + rr * FPAD + c8 * 8) =
                    *(const uint4*)(kg + (size_t)(m0 + rr) * DMODEL + c8 * 8);
                *(uint4*)(Vs + rr * FPAD + c8 * 8) =
                    *(const uint4*)(vg + (size_t)(m0 + rr) * DMODEL + c8 * 8);
            }
        }
        __syncthreads();

        // S = Q K^T  (warp: 32 rows x 32 kv cols)
        float s[2][4][4] = {};
#pragma unroll
        for (int ks = 0; ks < 4; ++ks) {
            uint32_t aq[2][4], bk[4][2];
            const int ar = wm * 32 + (lane & 15);
            const int ac = ks * 16 + (lane >> 4) * 8;
#pragma unroll
            for (int mt = 0; mt < 2; ++mt)
                ldm_x4(aq[mt], qbase + (uint32_t)((ar + mt * 16) * FPAD + ac) * 2);
            const int br = wn * 32 + (lane & 7);
            const int bc = ks * 16 + ((lane >> 3) & 1) * 8;
#pragma unroll
            for (int nt = 0; nt < 4; ++nt)
                ldm_x2(bk[nt], kbase + (uint32_t)((br + nt * 8) * FPAD + bc) * 2);
#pragma unroll
            for (int mt = 0; mt < 2; ++mt)
#pragma unroll
                for (int nt = 0; nt < 4; ++nt)
                    mma_f16(s[mt][nt], aq[mt], bk[nt]);
        }

        // row max (within warp's 32 cols)
        float rmax[2][2];
#pragma unroll
        for (int mt = 0; mt < 2; ++mt)
#pragma unroll
            for (int h = 0; h < 2; ++h) {
                float v = fmaxf(s[mt][0][h * 2], s[mt][0][h * 2 + 1]);
#pragma unroll
                for (int nt = 1; nt < 4; ++nt)
                    v = fmaxf(v, fmaxf(s[mt][nt][h * 2], s[mt][nt][h * 2 + 1]));
                v = fmaxf(v, __shfl_xor_sync(0xffffffffu, v, 1));
                v = fmaxf(v, __shfl_xor_sync(0xffffffffu, v, 2));
                rmax[mt][h] = v;
            }
        if (qd == 0) {
#pragma unroll
            for (int mt = 0; mt < 2; ++mt)
#pragma unroll
                for (int h = 0; h < 2; ++h)
                    red[wn * 128 + wm * 32 + mt * 16 + h * 8 + g] = rmax[mt][h];
        }
        __syncthreads();

        float fac[2][2], rsum[2][2];
#pragma unroll
        for (int mt = 0; mt < 2; ++mt)
#pragma unroll
            for (int h = 0; h < 2; ++h) {
                int row = wm * 32 + mt * 16 + h * 8 + g;
                float other = red[(wn ^ 1) * 128 + row];
                float nm = fmaxf(m_[mt][h], fmaxf(rmax[mt][h], other));
                fac[mt][h] = __expf(m_[mt][h] - nm);
                m_[mt][h] = nm;
                float sum = 0.f;
#pragma unroll
                for (int nt = 0; nt < 4; ++nt) {
                    float p0 = __expf(s[mt][nt][h * 2]     - nm);
                    float p1 = __expf(s[mt][nt][h * 2 + 1] - nm);
                    s[mt][nt][h * 2]     = p0;
                    s[mt][nt][h * 2 + 1] = p1;
                    sum += p0 + p1;
                }
                sum += __shfl_xor_sync(0xffffffffu, sum, 1);
                sum += __shfl_xor_sync(0xffffffffu, sum, 2);
                rsum[mt][h] = sum;
            }
        if (qd == 0) {
#pragma unroll
            for (int mt = 0; mt < 2; ++mt)
#pragma unroll
                for (int h = 0; h < 2; ++h)
                    red[256 + wn * 128 + wm * 32 + mt * 16 + h * 8 + g] = rsum[mt][h];
        }
        // rescale O
#pragma unroll
        for (int mt = 0; mt < 2; ++mt)
#pragma unroll
            for (int dn = 0; dn < 8; ++dn) {
                O[mt][dn][0] *= fac[mt][0];
                O[mt][dn][1] *= fac[mt][0];
                O[mt][dn][2] *= fac[mt][1];
                O[mt][dn][3] *= fac[mt][1];
            }
        __syncthreads();
#pragma unroll
        for (int mt = 0; mt < 2; ++mt)
#pragma unroll
            for (int h = 0; h < 2; ++h) {
                int row = wm * 32 + mt * 16 + h * 8 + g;
                l_[mt][h] = l_[mt][h] * fac[mt][h] + rsum[mt][h]
                          + red[256 + (wn ^ 1) * 128 + row];
            }

        // O += P * V  (P from S fragments, V via ldmatrix.trans)
#pragma unroll
        for (int kt = 0; kt < 2; ++kt) {
            uint32_t aP[2][4];
#pragma unroll
            for (int mt = 0; mt < 2; ++mt) {
                aP[mt][0] = pack_h2(s[mt][kt * 2][0],     s[mt][kt * 2][1]);
                aP[mt][1] = pack_h2(s[mt][kt * 2][2],     s[mt][kt * 2][3]);
                aP[mt][2] = pack_h2(s[mt][kt * 2 + 1][0], s[mt][kt * 2 + 1][1]);
                aP[mt][3] = pack_h2(s[mt][kt * 2 + 1][2], s[mt][kt * 2 + 1][3]);
            }
            const int vr = wn * 32 + kt * 16 + (lane & 7) + ((lane >> 3) & 1) * 8;
#pragma unroll
            for (int dn = 0; dn < 8; ++dn) {
                uint32_t bV[2];
                ldm_x2t(bV, vbase + (uint32_t)(vr * FPAD + dn * 8) * 2);
#pragma unroll
                for (int mt = 0; mt < 2; ++mt)
                    mma_f16(O[mt][dn], aP[mt], bV);
            }
        }
    }

    // Epilogue: O /= l, combine the two wn halves via smem, split to bf16 hi/lo.
#pragma unroll
    for (int mt = 0; mt < 2; ++mt) {
        float i0 = 1.f / l_[mt][0], i1 = 1.f / l_[mt][1];
#pragma unroll
        for (int dn = 0; dn < 8; ++dn) {
            O[mt][dn][0] *= i0; O[mt][dn][1] *= i0;
            O[mt][dn][2] *= i1; O[mt][dn][3] *= i1;
        }
    }
    __syncthreads();
    float* Os = (float*)fsm;     // 128 x 64 fp32 (32KB), aliases Qs/Ks/Vs
    if (wn == 0) {
#pragma unroll
        for (int mt = 0; mt < 2; ++mt)
#pragma unroll
            for (int dn = 0; dn < 8; ++dn) {
                int r = wm * 32 + mt * 16 + g;
                int c = dn * 8 + qd * 2;
                Os[r * 64 + c]           = O[mt][dn][0];
                Os[r * 64 + c + 1]       = O[mt][dn][1];
                Os[(r + 8) * 64 + c]     = O[mt][dn][2];
                Os[(r + 8) * 64 + c + 1] = O[mt][dn][3];
            }
    }
    __syncthreads();
    if (wn == 1) {
#pragma unroll
        for (int mt = 0; mt < 2; ++mt)
#pragma unroll
            for (int dn = 0; dn < 8; ++dn) {
                int r = wm * 32 + mt * 16 + g;
                int c = dn * 8 + qd * 2;
                Os[r * 64 + c]           += O[mt][dn][0];
                Os[r * 64 + c + 1]       += O[mt][dn][1];
                Os[(r + 8) * 64 + c]     += O[mt][dn][2];
                Os[(r + 8) * 64 + c + 1] += O[mt][dn][3];
            }
    }
    __syncthreads();

    {
        int r  = tid >> 1;
        int c0 = (tid & 1) * 32;
        size_t orow = (size_t)(b * NQ + q0 + r) * DMODEL + hh * DH + c0;
        __nv_bfloat16 hb[32], lb[32];
#pragma unroll
        for (int j = 0; j < 32; ++j) {
            float f = Os[r * 64 + c0 + j];
            __nv_bfloat16 h = __float2bfloat16(f);
            hb[j] = h;
            lb[j] = __float2bfloat16(f - __bfloat162float(h));
        }
#pragma unroll
        for (int j = 0; j < 4; ++j) {
            *(uint4*)(aoh + orow + j * 8) = *(uint4*)&hb[j * 8];
            *(uint4*)(aol + orow + j * 8) = *(uint4*)&lb[j * 8];
        }
    }
}

// ---------------------------------------------------------------------------
extern "C" void kernel_launch(void* const* d_in, const int* in_sizes, int n_in,
                              void* d_out, int out_size)
{
    const float* x   = (const float*)d_in[0];
    const float* ctx = (const float*)d_in[1];
    const float* Wq  = (const float*)d_in[2];
    const float* Wk  = (const float*)d_in[3];
    const float* Wv  = (const float*)d_in[4];
    const float* Wo  = (const float*)d_in[5];
    const float* bo  = (const float*)d_in[6];
    float* out = (float*)d_out;

    __nv_bfloat16 *xh, *xl, *ch, *cl, *wh, *wl, *aoh, *aol;
    __half *q16, *k16, *v16;
    cudaGetSymbolAddress((void**)&xh,  g_xh);
    cudaGetSymbolAddress((void**)&xl,  g_xl);
    cudaGetSymbolAddress((void**)&ch,  g_ch);
    cudaGetSymbolAddress((void**)&cl,  g_cl);
    cudaGetSymbolAddress((void**)&wh,  g_wh);
    cudaGetSymbolAddress((void**)&wl,  g_wl);
    cudaGetSymbolAddress((void**)&aoh, g_aoh);
    cudaGetSymbolAddress((void**)&aol, g_aol);
    cudaGetSymbolAddress((void**)&q16, g_q16);
    cudaGetSymbolAddress((void**)&k16, g_k16);
    cudaGetSymbolAddress((void**)&v16, g_v16);

    cudaFuncSetAttribute(gemm_mma, cudaFuncAttributeMaxDynamicSharedMemorySize, GEMM_DSMEM);

    const int NACT = ROWS_Q * DMODEL;   // 8388608
    const int NW   = DMODEL * DMODEL;   // 1048576
    const int TB   = 256;

    split_kernel<<<(NACT / 4 + TB - 1) / TB, TB>>>(x,   xh, xl, NACT / 4);
    split_kernel<<<(NACT / 4 + TB - 1) / TB, TB>>>(ctx, ch, cl, NACT / 4);
    split_kernel<<<(NW / 4 + TB - 1) / TB, TB>>>(Wq, wh + 0 * NW, wl + 0 * NW, NW / 4);
    split_kernel<<<(NW / 4 + TB - 1) / TB, TB>>>(Wk, wh + 1 * NW, wl + 1 * NW, NW / 4);
    split_kernel<<<(NW / 4 + TB - 1) / TB, TB>>>(Wv, wh + 2 * NW, wl + 2 * NW, NW / 4);
    split_kernel<<<(NW / 4 + TB - 1) / TB, TB>>>(Wo, wh + 3 * NW, wl + 3 * NW, NW / 4);

    dim3 ggrid(DMODEL / 128, ROWS_Q / 128);   // (8, 64)
    const float scale = 0.125f;               // 64^-0.5 folded into Q

    gemm_mma<<<ggrid, 256, GEMM_DSMEM>>>(xh, xl, wh + 0 * NW, wl + 0 * NW, q16, nullptr, scale, 1);
    gemm_mma<<<ggrid, 256, GEMM_DSMEM>>>(ch, cl, wh + 1 * NW, wl + 1 * NW, k16, nullptr, 1.0f, 1);
    gemm_mma<<<ggrid, 256, GEMM_DSMEM>>>(ch, cl, wh + 2 * NW, wl + 2 * NW, v16, nullptr, 1.0f, 1);

    flash_mma<<<dim3(NQ / 128, BATCH * HEADS), 256>>>(q16, k16, v16, aoh, aol);

    gemm_mma<<<ggrid, 256, GEMM_DSMEM>>>(aoh, aol, wh + 3 * NW, wl + 3 * NW, out, bo, 1.0f, 0);
}